// round 1
// baseline (speedup 1.0000x reference)
#include <cuda_runtime.h>

// Problem constants (fixed by setup_inputs)
#define HH 256
#define WW 256
#define KK 64
#define MV 16
#define NSTEPS 64
#define VOLR 256.0f
#define DTST (1.0f/256.0f)

// Scratch: channel-interleaved template [k][z][y][x] -> float4 (4 MB)
__device__ float4 g_tmpl[KK * MV * MV * MV];
// Per-prim params: 24 floats each
// [0..8] rot row-major R[i][j], [9..11] pos (normalized), [12..14] scale,
// [15..17] aabb min, [18..20] aabb max
__device__ float g_prim[KK * 24];

__global__ void pack_kernel(const float* __restrict__ primrgba) {
    int idx = blockIdx.x * blockDim.x + threadIdx.x;
    if (idx >= KK * MV * MV * MV) return;
    int k = idx >> 12;
    int v = idx & 4095;
    const float* base = primrgba + (size_t)k * 4 * 4096 + v;
    float4 val;
    val.x = base[0];
    val.y = base[4096];
    val.z = base[8192];
    val.w = base[12288];
    g_tmpl[idx] = val;
}

__global__ void prep_kernel(const float* __restrict__ primpos,
                            const float* __restrict__ primrot,
                            const float* __restrict__ primscale) {
    int k = threadIdx.x;
    if (k >= KK) return;
    float R[9];
#pragma unroll
    for (int i = 0; i < 9; i++) R[i] = primrot[k * 9 + i];
    float px = primpos[k * 3 + 0] / VOLR;
    float py = primpos[k * 3 + 1] / VOLR;
    float pz = primpos[k * 3 + 2] / VOLR;
    float sx = primscale[k * 3 + 0];
    float sy = primscale[k * 3 + 1];
    float sz = primscale[k * 3 + 2];
    float i0 = 1.0f / sx, i1 = 1.0f / sy, i2 = 1.0f / sz;
    // world half-extent along axis a: sum_j |R[a][j]| / scale_j
    float e0 = fabsf(R[0]) * i0 + fabsf(R[1]) * i1 + fabsf(R[2]) * i2;
    float e1 = fabsf(R[3]) * i0 + fabsf(R[4]) * i1 + fabsf(R[5]) * i2;
    float e2 = fabsf(R[6]) * i0 + fabsf(R[7]) * i1 + fabsf(R[8]) * i2;
    const float pad = 1e-4f;  // conservative: inside test is exact, AABB only culls
    float* P = g_prim + k * 24;
#pragma unroll
    for (int i = 0; i < 9; i++) P[i] = R[i];
    P[9] = px; P[10] = py; P[11] = pz;
    P[12] = sx; P[13] = sy; P[14] = sz;
    P[15] = px - e0 - pad; P[16] = py - e1 - pad; P[17] = pz - e2 - pad;
    P[18] = px + e0 + pad; P[19] = py + e1 + pad; P[20] = pz + e2 + pad;
    P[21] = 0.f; P[22] = 0.f; P[23] = 0.f;
}

__global__ __launch_bounds__(256) void march_kernel(
    const float* __restrict__ raypos,
    const float* __restrict__ raydir,
    const float* __restrict__ tminmax,
    float* __restrict__ out)
{
    __shared__ float sP[KK * 24];
    int tid = threadIdx.y * 16 + threadIdx.x;
    for (int i = tid; i < KK * 24; i += 256) sP[i] = g_prim[i];
    __syncthreads();

    int x = blockIdx.x * 16 + threadIdx.x;
    int y = blockIdx.y * 16 + threadIdx.y;
    int r = y * WW + x;

    float ox = raypos[r * 3 + 0], oy = raypos[r * 3 + 1], oz = raypos[r * 3 + 2];
    float dx = raydir[r * 3 + 0], dy = raydir[r * 3 + 1], dz = raydir[r * 3 + 2];
    float tmin = tminmax[r * 2 + 0], tmax = tminmax[r * 2 + 1];

    float o3[3] = {ox, oy, oz};
    float d3[3] = {dx, dy, dz};

    // Build per-ray active primitive list: 6b prim | 6b step_lo | 6b step_hi
    unsigned int list[KK];
    int nact = 0;
#pragma unroll 1
    for (int k = 0; k < KK; k++) {
        const float* P = sP + k * 24;
        float t0 = tmin, t1 = tmax;
        bool miss = false;
#pragma unroll
        for (int a = 0; a < 3; a++) {
            float mn = P[15 + a], mx = P[18 + a];
            float da = d3[a], oa = o3[a];
            if (fabsf(da) > 1e-9f) {
                float inv = 1.0f / da;
                float ta = (mn - oa) * inv;
                float tb = (mx - oa) * inv;
                t0 = fmaxf(t0, fminf(ta, tb));
                t1 = fminf(t1, fmaxf(ta, tb));
            } else if (oa < mn || oa > mx) {
                miss = true;
            }
        }
        if (miss || t0 > t1) continue;
        // conservative step range: t_i = tmin + (i+0.5)*DT
        int ilo = (int)floorf((t0 - tmin) * 256.0f - 0.5f);
        int ihi = (int)ceilf((t1 - tmin) * 256.0f - 0.5f);
        ilo = max(ilo, 0);
        ihi = min(ihi, NSTEPS - 1);
        if (ilo > ihi) continue;
        list[nact++] = (unsigned)k | ((unsigned)ilo << 6) | ((unsigned)ihi << 12);
    }

    float rgb0 = 0.f, rgb1 = 0.f, rgb2 = 0.f, alpha = 0.f;

#pragma unroll 1
    for (int i = 0; i < NSTEPS; i++) {
        float t = fmaf((float)i + 0.5f, DTST, tmin);
        if (t >= tmax) break;  // t is monotone: all later steps invalid too
        float px = fmaf(t, dx, ox);
        float py = fmaf(t, dy, oy);
        float pz = fmaf(t, dz, oz);

        float sx = 0.f, sy = 0.f, sz = 0.f, sw = 0.f;
#pragma unroll 1
        for (int a = 0; a < nact; a++) {
            unsigned u = list[a];
            unsigned ilo = (u >> 6) & 63u;
            unsigned ihi = (u >> 12) & 63u;
            if ((unsigned)i < ilo || (unsigned)i > ihi) continue;
            int k = (int)(u & 63u);
            const float* P = sP + k * 24;
            float rx = px - P[9], ry = py - P[10], rz = pz - P[11];
            // local_j = sum_i rel_i * R[i][j], scaled
            float lx = (rx * P[0] + ry * P[3] + rz * P[6]) * P[12];
            float ly = (rx * P[1] + ry * P[4] + rz * P[7]) * P[13];
            float lz = (rx * P[2] + ry * P[5] + rz * P[8]) * P[14];
            if (!(fabsf(lx) < 1.0f && fabsf(ly) < 1.0f && fabsf(lz) < 1.0f)) continue;

            float gx = fminf(fmaxf((lx + 1.0f) * 0.5f * 15.0f, 0.0f), 14.99999f);
            float gy = fminf(fmaxf((ly + 1.0f) * 0.5f * 15.0f, 0.0f), 14.99999f);
            float gz = fminf(fmaxf((lz + 1.0f) * 0.5f * 15.0f, 0.0f), 14.99999f);
            int x0 = min((int)gx, MV - 2);
            int y0 = min((int)gy, MV - 2);
            int z0 = min((int)gz, MV - 2);
            float fx = gx - (float)x0;
            float fy = gy - (float)y0;
            float fz = gz - (float)z0;

            const float4* T = g_tmpl + (((k * MV + z0) * MV + y0) * MV + x0);
            float4 c000 = T[0],   c001 = T[1];
            float4 c010 = T[16],  c011 = T[17];
            float4 c100 = T[256], c101 = T[257];
            float4 c110 = T[272], c111 = T[273];

            float wz0 = 1.0f - fz, wz1 = fz;
            float wy0 = 1.0f - fy, wy1 = fy;
            float wx0 = 1.0f - fx, wx1 = fx;
            float w000 = wz0 * wy0 * wx0, w001 = wz0 * wy0 * wx1;
            float w010 = wz0 * wy1 * wx0, w011 = wz0 * wy1 * wx1;
            float w100 = wz1 * wy0 * wx0, w101 = wz1 * wy0 * wx1;
            float w110 = wz1 * wy1 * wx0, w111 = wz1 * wy1 * wx1;

            sx = fmaf(c000.x, w000, sx); sy = fmaf(c000.y, w000, sy);
            sz = fmaf(c000.z, w000, sz); sw = fmaf(c000.w, w000, sw);
            sx = fmaf(c001.x, w001, sx); sy = fmaf(c001.y, w001, sy);
            sz = fmaf(c001.z, w001, sz); sw = fmaf(c001.w, w001, sw);
            sx = fmaf(c010.x, w010, sx); sy = fmaf(c010.y, w010, sy);
            sz = fmaf(c010.z, w010, sz); sw = fmaf(c010.w, w010, sw);
            sx = fmaf(c011.x, w011, sx); sy = fmaf(c011.y, w011, sy);
            sz = fmaf(c011.z, w011, sz); sw = fmaf(c011.w, w011, sw);
            sx = fmaf(c100.x, w100, sx); sy = fmaf(c100.y, w100, sy);
            sz = fmaf(c100.z, w100, sz); sw = fmaf(c100.w, w100, sw);
            sx = fmaf(c101.x, w101, sx); sy = fmaf(c101.y, w101, sy);
            sz = fmaf(c101.z, w101, sz); sw = fmaf(c101.w, w101, sw);
            sx = fmaf(c110.x, w110, sx); sy = fmaf(c110.y, w110, sy);
            sz = fmaf(c110.z, w110, sz); sw = fmaf(c110.w, w110, sw);
            sx = fmaf(c111.x, w111, sx); sy = fmaf(c111.y, w111, sy);
            sz = fmaf(c111.z, w111, sz); sw = fmaf(c111.w, w111, sw);
        }

        float contrib = fminf(1.0f, fmaf(sw, DTST, alpha)) - alpha;
        rgb0 = fmaf(sx, contrib, rgb0);
        rgb1 = fmaf(sy, contrib, rgb1);
        rgb2 = fmaf(sz, contrib, rgb2);
        alpha += contrib;
    }

    const int HWsz = HH * WW;
    // rayrgb (1,3,H,W)
    out[0 * HWsz + r] = rgb0;
    out[1 * HWsz + r] = rgb1;
    out[2 * HWsz + r] = rgb2;
    // rayalpha (1,1,H,W)
    out[3 * HWsz + r] = alpha;
    // rayrgba (1,4,H,W)
    out[4 * HWsz + r] = rgb0;
    out[5 * HWsz + r] = rgb1;
    out[6 * HWsz + r] = rgb2;
    out[7 * HWsz + r] = alpha;
}

extern "C" void kernel_launch(void* const* d_in, const int* in_sizes, int n_in,
                              void* d_out, int out_size) {
    const float* raypos    = (const float*)d_in[0];
    const float* raydir    = (const float*)d_in[1];
    const float* tminmax   = (const float*)d_in[2];
    const float* primpos   = (const float*)d_in[3];
    const float* primrot   = (const float*)d_in[4];
    const float* primscale = (const float*)d_in[5];
    const float* primrgba  = (const float*)d_in[6];
    float* out = (float*)d_out;

    pack_kernel<<<(KK * MV * MV * MV + 255) / 256, 256>>>(primrgba);
    prep_kernel<<<1, 64>>>(primpos, primrot, primscale);
    dim3 grid(WW / 16, HH / 16);
    dim3 block(16, 16);
    march_kernel<<<grid, block>>>(raypos, raydir, tminmax, out);
}

// round 3
// speedup vs baseline: 34.8527x; 34.8527x over previous
#include <cuda_runtime.h>

#define HH 256
#define WW 256
#define KK 64
#define MV 16
#define NSTEPS 64
#define VOLR 256.0f
#define DTST (1.0f/256.0f)

// Channel-interleaved template [k][z][y][x] -> float4 (4 MB, L2-resident)
__device__ float4 g_tmpl[KK * MV * MV * MV];
// Per-prim params: [0..8] R row-major, [9..11] pos, [12..14] scale,
// [15..17] aabb min, [18..20] aabb max
__device__ float g_prim[KK * 24];

__global__ void pack_kernel(const float* __restrict__ primrgba) {
    int idx = blockIdx.x * blockDim.x + threadIdx.x;
    if (idx >= KK * MV * MV * MV) return;
    int k = idx >> 12;
    int v = idx & 4095;
    const float* base = primrgba + (size_t)k * 4 * 4096 + v;
    float4 val;
    val.x = base[0];
    val.y = base[4096];
    val.z = base[8192];
    val.w = base[12288];
    g_tmpl[idx] = val;
}

__global__ void prep_kernel(const float* __restrict__ primpos,
                            const float* __restrict__ primrot,
                            const float* __restrict__ primscale) {
    int k = threadIdx.x;
    if (k >= KK) return;
    float R[9];
#pragma unroll
    for (int i = 0; i < 9; i++) R[i] = primrot[k * 9 + i];
    float px = primpos[k * 3 + 0] / VOLR;
    float py = primpos[k * 3 + 1] / VOLR;
    float pz = primpos[k * 3 + 2] / VOLR;
    float sx = primscale[k * 3 + 0];
    float sy = primscale[k * 3 + 1];
    float sz = primscale[k * 3 + 2];
    float i0 = 1.0f / sx, i1 = 1.0f / sy, i2 = 1.0f / sz;
    float e0 = fabsf(R[0]) * i0 + fabsf(R[1]) * i1 + fabsf(R[2]) * i2;
    float e1 = fabsf(R[3]) * i0 + fabsf(R[4]) * i1 + fabsf(R[5]) * i2;
    float e2 = fabsf(R[6]) * i0 + fabsf(R[7]) * i1 + fabsf(R[8]) * i2;
    const float pad = 1e-4f;
    float* P = g_prim + k * 24;
#pragma unroll
    for (int i = 0; i < 9; i++) P[i] = R[i];
    P[9] = px; P[10] = py; P[11] = pz;
    P[12] = sx; P[13] = sy; P[14] = sz;
    P[15] = px - e0 - pad; P[16] = py - e1 - pad; P[17] = pz - e2 - pad;
    P[18] = px + e0 + pad; P[19] = py + e1 + pad; P[20] = pz + e2 + pad;
    P[21] = 0.f; P[22] = 0.f; P[23] = 0.f;
}

// Evaluate one prim at one point, accumulate 4-channel sample.
__device__ __forceinline__ void eval_prim(
    const float* __restrict__ P, int k,
    float px, float py, float pz, float s[4])
{
    float rx = px - P[9], ry = py - P[10], rz = pz - P[11];
    float lx = (rx * P[0] + ry * P[3] + rz * P[6]) * P[12];
    float ly = (rx * P[1] + ry * P[4] + rz * P[7]) * P[13];
    float lz = (rx * P[2] + ry * P[5] + rz * P[8]) * P[14];
    if (!(fabsf(lx) < 1.0f && fabsf(ly) < 1.0f && fabsf(lz) < 1.0f)) return;

    float gx = fminf(fmaxf((lx + 1.0f) * 0.5f * 15.0f, 0.0f), 14.99999f);
    float gy = fminf(fmaxf((ly + 1.0f) * 0.5f * 15.0f, 0.0f), 14.99999f);
    float gz = fminf(fmaxf((lz + 1.0f) * 0.5f * 15.0f, 0.0f), 14.99999f);
    int x0 = min((int)gx, MV - 2);
    int y0 = min((int)gy, MV - 2);
    int z0 = min((int)gz, MV - 2);
    float fx = gx - (float)x0;
    float fy = gy - (float)y0;
    float fz = gz - (float)z0;

    const float4* T = g_tmpl + (((k * MV + z0) * MV + y0) * MV + x0);
    float4 c000 = __ldg(T + 0),   c001 = __ldg(T + 1);
    float4 c010 = __ldg(T + 16),  c011 = __ldg(T + 17);
    float4 c100 = __ldg(T + 256), c101 = __ldg(T + 257);
    float4 c110 = __ldg(T + 272), c111 = __ldg(T + 273);

    float wz0 = 1.0f - fz, wy0 = 1.0f - fy, wx0 = 1.0f - fx;
    float w000 = wz0 * wy0 * wx0, w001 = wz0 * wy0 * fx;
    float w010 = wz0 * fy * wx0,  w011 = wz0 * fy * fx;
    float w100 = fz * wy0 * wx0,  w101 = fz * wy0 * fx;
    float w110 = fz * fy * wx0,   w111 = fz * fy * fx;

    s[0] = fmaf(c000.x, w000, s[0]); s[1] = fmaf(c000.y, w000, s[1]);
    s[2] = fmaf(c000.z, w000, s[2]); s[3] = fmaf(c000.w, w000, s[3]);
    s[0] = fmaf(c001.x, w001, s[0]); s[1] = fmaf(c001.y, w001, s[1]);
    s[2] = fmaf(c001.z, w001, s[2]); s[3] = fmaf(c001.w, w001, s[3]);
    s[0] = fmaf(c010.x, w010, s[0]); s[1] = fmaf(c010.y, w010, s[1]);
    s[2] = fmaf(c010.z, w010, s[2]); s[3] = fmaf(c010.w, w010, s[3]);
    s[0] = fmaf(c011.x, w011, s[0]); s[1] = fmaf(c011.y, w011, s[1]);
    s[2] = fmaf(c011.z, w011, s[2]); s[3] = fmaf(c011.w, w011, s[3]);
    s[0] = fmaf(c100.x, w100, s[0]); s[1] = fmaf(c100.y, w100, s[1]);
    s[2] = fmaf(c100.z, w100, s[2]); s[3] = fmaf(c100.w, w100, s[3]);
    s[0] = fmaf(c101.x, w101, s[0]); s[1] = fmaf(c101.y, w101, s[1]);
    s[2] = fmaf(c101.z, w101, s[2]); s[3] = fmaf(c101.w, w101, s[3]);
    s[0] = fmaf(c110.x, w110, s[0]); s[1] = fmaf(c110.y, w110, s[1]);
    s[2] = fmaf(c110.z, w110, s[2]); s[3] = fmaf(c110.w, w110, s[3]);
    s[0] = fmaf(c111.x, w111, s[0]); s[1] = fmaf(c111.y, w111, s[1]);
    s[2] = fmaf(c111.z, w111, s[2]); s[3] = fmaf(c111.w, w111, s[3]);
}

__device__ __forceinline__ bool slab_test(
    const float* __restrict__ P,
    float ox, float oy, float oz,
    float dx, float dy, float dz,
    float tmin, float tmax)
{
    float o3[3] = {ox, oy, oz};
    float d3[3] = {dx, dy, dz};
    float t0 = tmin, t1 = tmax;
#pragma unroll
    for (int a = 0; a < 3; a++) {
        float mn = P[15 + a], mx = P[18 + a];
        float da = d3[a], oa = o3[a];
        if (fabsf(da) > 1e-9f) {
            float inv = 1.0f / da;
            float ta = (mn - oa) * inv;
            float tb = (mx - oa) * inv;
            t0 = fmaxf(t0, fminf(ta, tb));
            t1 = fminf(t1, fmaxf(ta, tb));
        } else if (oa < mn || oa > mx) {
            return false;
        }
    }
    return t0 <= t1;
}

// One warp per ray; lane owns steps {lane, lane+32}.
__global__ __launch_bounds__(256) void march_kernel(
    const float* __restrict__ raypos,
    const float* __restrict__ raydir,
    const float* __restrict__ tminmax,
    float* __restrict__ out)
{
    __shared__ float sP[KK * 24];
    for (int i = threadIdx.x; i < KK * 24; i += 256) sP[i] = g_prim[i];
    __syncthreads();

    int lane = threadIdx.x & 31;
    int warpId = threadIdx.x >> 5;
    int r = blockIdx.x * 8 + warpId;  // ray index, row-major over H*W

    float ox = raypos[r * 3 + 0], oy = raypos[r * 3 + 1], oz = raypos[r * 3 + 2];
    float dx = raydir[r * 3 + 0], dy = raydir[r * 3 + 1], dz = raydir[r * 3 + 2];
    float tmin = tminmax[r * 2 + 0], tmax = tminmax[r * 2 + 1];

    // Cooperative AABB cull: lane tests prims {lane, lane+32}
    bool a0 = slab_test(sP + lane * 24,        ox, oy, oz, dx, dy, dz, tmin, tmax);
    bool a1 = slab_test(sP + (lane + 32) * 24, ox, oy, oz, dx, dy, dz, tmin, tmax);
    unsigned m0 = __ballot_sync(0xFFFFFFFFu, a0);
    unsigned m1 = __ballot_sync(0xFFFFFFFFu, a1);
    unsigned long long mask = (unsigned long long)m0 |
                              ((unsigned long long)m1 << 32);

    // Two sample points per lane
    float t0 = fmaf((float)lane + 0.5f,  DTST, tmin);
    float t1 = fmaf((float)lane + 32.5f, DTST, tmin);
    float p0x = fmaf(t0, dx, ox), p0y = fmaf(t0, dy, oy), p0z = fmaf(t0, dz, oz);
    float p1x = fmaf(t1, dx, ox), p1y = fmaf(t1, dy, oy), p1z = fmaf(t1, dz, oz);

    float s0[4] = {0.f, 0.f, 0.f, 0.f};
    float s1[4] = {0.f, 0.f, 0.f, 0.f};

    while (mask) {
        int k = __ffsll(mask) - 1;
        mask &= mask - 1;
        const float* P = sP + k * 24;
        eval_prim(P, k, p0x, p0y, p0z, s0);
        eval_prim(P, k, p1x, p1y, p1z, s1);
    }

    // Alpha compositing via prefix sum: alpha_i = min(1, sum_{j<=i} d_j)
    float d0 = (t0 < tmax) ? s0[3] * DTST : 0.f;
    float d1 = (t1 < tmax) ? s1[3] * DTST : 0.f;

    float c0 = d0;
#pragma unroll
    for (int off = 1; off < 32; off <<= 1) {
        float v = __shfl_up_sync(0xFFFFFFFFu, c0, off);
        if (lane >= off) c0 += v;
    }
    float tot0 = __shfl_sync(0xFFFFFFFFu, c0, 31);
    float c1 = d1;
#pragma unroll
    for (int off = 1; off < 32; off <<= 1) {
        float v = __shfl_up_sync(0xFFFFFFFFu, c1, off);
        if (lane >= off) c1 += v;
    }
    float S0 = c0;            // inclusive prefix at step lane
    float S1 = tot0 + c1;     // inclusive prefix at step lane+32
    float contrib0 = fminf(1.f, S0) - fminf(1.f, S0 - d0);
    float contrib1 = fminf(1.f, S1) - fminf(1.f, S1 - d1);

    float rgbx = s0[0] * contrib0 + s1[0] * contrib1;
    float rgby = s0[1] * contrib0 + s1[1] * contrib1;
    float rgbz = s0[2] * contrib0 + s1[2] * contrib1;

#pragma unroll
    for (int off = 16; off > 0; off >>= 1) {
        rgbx += __shfl_xor_sync(0xFFFFFFFFu, rgbx, off);
        rgby += __shfl_xor_sync(0xFFFFFFFFu, rgby, off);
        rgbz += __shfl_xor_sync(0xFFFFFFFFu, rgbz, off);
    }
    float alphaF = fminf(1.f, __shfl_sync(0xFFFFFFFFu, S1, 31));

    if (lane == 0) {
        const int HWsz = HH * WW;
        out[0 * HWsz + r] = rgbx;
        out[1 * HWsz + r] = rgby;
        out[2 * HWsz + r] = rgbz;
        out[3 * HWsz + r] = alphaF;
        out[4 * HWsz + r] = rgbx;
        out[5 * HWsz + r] = rgby;
        out[6 * HWsz + r] = rgbz;
        out[7 * HWsz + r] = alphaF;
    }
}

extern "C" void kernel_launch(void* const* d_in, const int* in_sizes, int n_in,
                              void* d_out, int out_size) {
    const float* raypos    = (const float*)d_in[0];
    const float* raydir    = (const float*)d_in[1];
    const float* tminmax   = (const float*)d_in[2];
    const float* primpos   = (const float*)d_in[3];
    const float* primrot   = (const float*)d_in[4];
    const float* primscale = (const float*)d_in[5];
    const float* primrgba  = (const float*)d_in[6];
    float* out = (float*)d_out;

    pack_kernel<<<(KK * MV * MV * MV + 255) / 256, 256>>>(primrgba);
    prep_kernel<<<1, 64>>>(primpos, primrot, primscale);
    march_kernel<<<HH * WW / 8, 256>>>(raypos, raydir, tminmax, out);
}